// round 7
// baseline (speedup 1.0000x reference)
#include <cuda_runtime.h>
#include <cuda_fp16.h>
#include <math.h>

#define BB    128
#define TT    2048
#define KD    128
#define VD    128
#define HD    300
#define ED    400
#define NV    33
#define G4    1200
#define SOS   5
#define STEPS 500
#define NBLK  128
#define NTHR  1024
#define TRB   256   // transpose blocks in init

// ---------------- persistent device state ----------------
__device__ float g_hA[BB * HD];
__device__ float g_hB[BB * HD];
__device__ float g_c[BB * HD];
__device__ float g_ctx[BB * VD];
__device__ float g_ge[NV * G4];   // emb @ W_ih[:, :400]^T + b_ih + b_hh
__device__ int   g_char[BB];
__device__ unsigned g_count;
__device__ volatile unsigned g_sense;
// fp16 batch-major copies [b][t][k], stored as uint4 (8 halves) for hard
// 16-byte alignment (LDG.128/STG.128 safe).
__device__ uint4 g_keys4[(size_t)BB * TT * (KD / 8)];
__device__ uint4 g_vals4[(size_t)BB * TT * (VD / 8)];

union U4 { uint4 u; __half2 h[4]; };

__device__ __forceinline__ float sigf(float x) { return 1.f / (1.f + __expf(-x)); }
__device__ __forceinline__ float tanf_(float x) { return 2.f / (1.f + __expf(-2.f * x)) - 1.f; }

// ---------------- grid barrier (monotonic epoch) ----------------
__device__ __forceinline__ void gbar(unsigned e) {
    __syncthreads();
    if (threadIdx.x == 0) {
        __threadfence();
        unsigned prev = atomicAdd(&g_count, 1u);
        if (prev == e * NBLK - 1u) {
            g_sense = e;
        } else {
            while (g_sense < e) { }
        }
        __threadfence();
    }
    __syncthreads();
}

// ---------------- init: precompute + transpose + state reset ----------------
__global__ void init_kernel(const float* __restrict__ keys,
                            const float* __restrict__ values,
                            const float* __restrict__ emb,
                            const float* __restrict__ W_ih,
                            const float* __restrict__ b_ih,
                            const float* __restrict__ b_hh,
                            const float* __restrict__ h0,
                            const float* __restrict__ c0) {
    int blk = blockIdx.x, tid = threadIdx.x;
    if (blk < NV) {
        __shared__ float e_s[ED];
        for (int i = tid; i < ED; i += blockDim.x) e_s[i] = emb[blk * ED + i];
        __syncthreads();
        int wid = tid >> 5, lane = tid & 31;
        for (int j = wid; j < G4; j += 8) {
            float acc = 0.f;
            const float* wr = W_ih + (size_t)j * 528;
            for (int k = lane; k < ED; k += 32) acc += e_s[k] * wr[k];
            #pragma unroll
            for (int o = 16; o; o >>= 1) acc += __shfl_xor_sync(0xffffffffu, acc, o);
            if (lane == 0) g_ge[blk * G4 + j] = acc + b_ih[j] + b_hh[j];
        }
    } else if (blk == NV) {
        for (int i = tid; i < BB * HD; i += blockDim.x) {
            g_hA[i] = h0[i % HD];
            g_c[i]  = c0[i % HD];
        }
        for (int i = tid; i < BB; i += blockDim.x) g_char[i] = SOS;
        if (tid == 0) { g_count = 0u; g_sense = 0u; }
    } else {
        // transpose+convert: [t][b][k] f32 -> [b][t][k] f16, 8 elems per chunk
        const int CH = TT * BB * KD / 8;            // chunks per tensor
        int xb = blk - NV - 1;
        for (int c = xb * blockDim.x + tid; c < 2 * CH; c += TRB * blockDim.x) {
            int isV = c >= CH;
            int cc = isV ? c - CH : c;
            const float4* src = (const float4*)(isV ? values : keys) + (size_t)cc * 2;
            float4 a = src[0], b4 = src[1];
            U4 o;
            o.h[0] = __floats2half2_rn(a.x, a.y);
            o.h[1] = __floats2half2_rn(a.z, a.w);
            o.h[2] = __floats2half2_rn(b4.x, b4.y);
            o.h[3] = __floats2half2_rn(b4.z, b4.w);
            int kc = cc & 15;                // k-chunk (8 halves)
            int b  = (cc >> 4) & 127;
            int t  = cc >> 11;
            uint4* dst = isV ? g_vals4 : g_keys4;
            dst[((size_t)b * TT + t) * 16 + kc] = o.u;
        }
    }
}

// ---------------- attend phase: fused online-softmax sweep ----------------
__device__ void attend_phase(int b, const float* __restrict__ hbuf, int s,
                             const float* __restrict__ W_phi,
                             const float* __restrict__ b_phi,
                             const float* __restrict__ W_proj,
                             const float* __restrict__ b_proj,
                             float* __restrict__ out, int write_preds,
                             float* sm) {
    int tid = threadIdx.x, wid = tid >> 5, lane = tid & 31;
    float* cpart = sm;          // 4096 (32 warps * 128)
    float* h_s   = sm + 4096;   // 304
    float* q_s   = sm + 4400;   // 128 (16B aligned)
    float* ctx_s = sm + 4528;   // 128
    float* lg_s  = sm + 4656;   // 36
    float* redm  = sm + 4692;   // 32
    float* reds  = sm + 4724;   // 32

    for (int i = tid; i < HD; i += NTHR) h_s[i] = __ldcg(&hbuf[b * HD + i]);
    for (int i = tid; i < VD; i += NTHR) ctx_s[i] = __ldcg(&g_ctx[b * VD + i]);
    __syncthreads();

    if (s >= 0) {
        // logits: h_new + previous context
        for (int v = wid; v < NV; v += 32) {
            float acc = 0.f;
            const float* wr = W_proj + (size_t)v * 428;
            for (int k = lane; k < 428; k += 32) {
                float x = (k < HD) ? h_s[k] : ctx_s[k - HD];
                acc += x * wr[k];
            }
            #pragma unroll
            for (int o = 16; o; o >>= 1) acc += __shfl_xor_sync(0xffffffffu, acc, o);
            if (lane == 0) lg_s[v] = acc + b_proj[v];
        }
        __syncthreads();
        if (tid < NV) out[(size_t)s * (BB * NV) + b * NV + tid] = lg_s[tid];
        if (tid == 0) {
            int am = 0; float mv = lg_s[0];
            for (int v = 1; v < NV; ++v) if (lg_s[v] > mv) { mv = lg_s[v]; am = v; }
            __stcg(&g_char[b], am);
            if (write_preds)
                out[(size_t)STEPS * BB * NV + (size_t)s * BB + b] = (float)am;
        }
    }

    // query = h @ W_phi^T + b_phi
    for (int q = wid; q < KD; q += 32) {
        float acc = 0.f;
        const float* wr = W_phi + (size_t)q * HD;
        for (int k = lane; k < HD; k += 32) acc += h_s[k] * wr[k];
        #pragma unroll
        for (int o = 16; o; o >>= 1) acc += __shfl_xor_sync(0xffffffffu, acc, o);
        if (lane == 0) q_s[q] = acc + b_phi[q];
    }
    __syncthreads();

    // ---- fused sweep: keys+values streamed together, online softmax ----
    // 32 warps x 8 t per round, t-batch of 4 per parity half (fits 64-reg cap)
    {
        int kc = lane & 15;         // k/v chunk of 8 halves
        int ts = lane >> 4;         // t parity within iteration
        float4 qa = ((const float4*)q_s)[kc * 2];
        float4 qb = ((const float4*)q_s)[kc * 2 + 1];
        const uint4* kb = g_keys4 + (size_t)b * TT * 16;
        const uint4* vb = g_vals4 + (size_t)b * TT * 16;

        float m = -1e30f, ssum = 0.f;
        float va[8];
        #pragma unroll
        for (int j = 0; j < 8; j++) va[j] = 0.f;

        for (int t0 = wid * 8; t0 < TT; t0 += 256) {
            U4 kv[4], vv[4];
            #pragma unroll
            for (int i = 0; i < 4; i++) {
                size_t off = (size_t)(t0 + 2 * i + ts) * 16 + kc;
                kv[i].u = __ldg(&kb[off]);
                vv[i].u = __ldg(&vb[off]);
            }
            float e[4];
            #pragma unroll
            for (int i = 0; i < 4; i++) {
                float2 f0 = __half22float2(kv[i].h[0]);
                float2 f1 = __half22float2(kv[i].h[1]);
                float2 f2 = __half22float2(kv[i].h[2]);
                float2 f3 = __half22float2(kv[i].h[3]);
                e[i] = f0.x * qa.x + f0.y * qa.y + f1.x * qa.z + f1.y * qa.w
                     + f2.x * qb.x + f2.y * qb.y + f3.x * qb.z + f3.y * qb.w;
            }
            #pragma unroll
            for (int o = 8; o; o >>= 1) {
                #pragma unroll
                for (int i = 0; i < 4; i++)
                    e[i] += __shfl_xor_sync(0xffffffffu, e[i], o);
            }
            // block max across both t-parity halves (warp-uniform)
            float bm = e[0];
            #pragma unroll
            for (int i = 1; i < 4; i++) bm = fmaxf(bm, e[i]);
            bm = fmaxf(bm, __shfl_xor_sync(0xffffffffu, bm, 16));
            float mn = fmaxf(m, bm);
            float sc = __expf(m - mn);
            m = mn;
            float w[4], ls = 0.f;
            #pragma unroll
            for (int i = 0; i < 4; i++) { w[i] = __expf(e[i] - mn); ls += w[i]; }
            ssum = ssum * sc + ls;
            #pragma unroll
            for (int j = 0; j < 8; j++) va[j] *= sc;
            #pragma unroll
            for (int i = 0; i < 4; i++) {
                float2 f0 = __half22float2(vv[i].h[0]);
                float2 f1 = __half22float2(vv[i].h[1]);
                float2 f2 = __half22float2(vv[i].h[2]);
                float2 f3 = __half22float2(vv[i].h[3]);
                va[0] += w[i] * f0.x; va[1] += w[i] * f0.y;
                va[2] += w[i] * f1.x; va[3] += w[i] * f1.y;
                va[4] += w[i] * f2.x; va[5] += w[i] * f2.y;
                va[6] += w[i] * f3.x; va[7] += w[i] * f3.y;
            }
        }
        // merge t-parity halves (same m across warp)
        ssum += __shfl_xor_sync(0xffffffffu, ssum, 16);
        #pragma unroll
        for (int j = 0; j < 8; j++)
            va[j] += __shfl_xor_sync(0xffffffffu, va[j], 16);
        if (ts == 0) {
            #pragma unroll
            for (int j = 0; j < 8; j++) cpart[wid * 128 + kc * 8 + j] = va[j];
        }
        if (lane == 0) { redm[wid] = m; reds[wid] = ssum; }
    }
    __syncthreads();

    // final cross-warp combine
    if (tid < 128) {
        float M = redm[0];
        #pragma unroll
        for (int w = 1; w < 32; w++) M = fmaxf(M, redm[w]);
        float S = 0.f, cx = 0.f;
        #pragma unroll
        for (int w = 0; w < 32; w++) {
            float f = __expf(redm[w] - M);
            S += reds[w] * f;
            cx += cpart[w * 128 + tid] * f;
        }
        __stcg(&g_ctx[b * VD + tid], cx / S);
    }
    __syncthreads();
}

// ---------------- LSTM phase ----------------
__device__ void lstm_phase(int parity,
                           const float* __restrict__ W_ih,
                           const float* __restrict__ W_hh,
                           float* sm) {
    int cta = blockIdx.x;
    if (cta >= 120) return;           // whole CTA exits: per-CTA syncs unaffected
    int tid = threadIdx.x;
    int bt = cta / 15;
    int nt = cta % 15;
    const float* h_in  = parity ? g_hB : g_hA;
    float*       h_out = parity ? g_hA : g_hB;

    float* xx = sm;             // [16][432] = 6912 floats
    for (int idx = tid; idx < 16 * 428; idx += NTHR) {
        int bl = idx / 428, k = idx - bl * 428;
        int bg = bt * 16 + bl;
        float v = (k < 128) ? __ldcg(&g_ctx[bg * 128 + k])
                            : __ldcg(&h_in[bg * 300 + (k - 128)]);
        xx[bl * 432 + k] = v;
    }
    __syncthreads();

    float acc[4][4];
    int ks = 0, rem = 0;
    if (tid < 320) {
        ks = tid / 80; rem = tid % 80;
        int rg = rem / 4, bg = rem % 4;
        int gq = (rg * 4) / 20, rl = (rg * 4) % 20;
        int row0 = gq * 300 + nt * 20 + rl;
        #pragma unroll
        for (int r = 0; r < 4; r++)
            #pragma unroll
            for (int bi = 0; bi < 4; bi++) acc[r][bi] = 0.f;

        int k4s = ks * 27, k4e = (ks == 3) ? 107 : (k4s + 27);
        const float4* xb[4];
        #pragma unroll
        for (int bi = 0; bi < 4; bi++)
            xb[bi] = (const float4*)(xx + (size_t)(bg * 4 + bi) * 432);

        int e1 = k4e < 32 ? k4e : 32;
        for (int k4 = k4s; k4 < e1; k4++) {
            float4 w[4];
            #pragma unroll
            for (int r = 0; r < 4; r++)
                w[r] = __ldg((const float4*)(W_ih + (size_t)(row0 + r) * 528 + 400) + k4);
            #pragma unroll
            for (int bi = 0; bi < 4; bi++) {
                float4 x = xb[bi][k4];
                #pragma unroll
                for (int r = 0; r < 4; r++)
                    acc[r][bi] += w[r].x * x.x + w[r].y * x.y + w[r].z * x.z + w[r].w * x.w;
            }
        }
        int s2 = k4s > 32 ? k4s : 32;
        for (int k4 = s2; k4 < k4e; k4++) {
            float4 w[4];
            #pragma unroll
            for (int r = 0; r < 4; r++)
                w[r] = __ldg((const float4*)(W_hh + (size_t)(row0 + r) * 300) + (k4 - 32));
            #pragma unroll
            for (int bi = 0; bi < 4; bi++) {
                float4 x = xb[bi][k4];
                #pragma unroll
                for (int r = 0; r < 4; r++)
                    acc[r][bi] += w[r].x * x.x + w[r].y * x.y + w[r].z * x.z + w[r].w * x.w;
            }
        }
    }
    __syncthreads();

    float* part = sm;           // 5120 floats
    float* gs   = sm + 5120;    // 1280 floats
    if (tid < 320) {
        #pragma unroll
        for (int r = 0; r < 4; r++)
            #pragma unroll
            for (int bi = 0; bi < 4; bi++)
                part[(rem * 16 + r * 4 + bi) * 4 + ks] = acc[r][bi];
    }
    __syncthreads();

    for (int o = tid; o < 1280; o += NTHR) {
        float sum = part[o * 4] + part[o * 4 + 1] + part[o * 4 + 2] + part[o * 4 + 3];
        int rm = o >> 4, ri = (o >> 2) & 3, bi = o & 3;
        int rg = rm >> 2, bg = rm & 3;
        int r = rg * 4 + ri;
        int bl = bg * 4 + bi;
        int gq = r / 20, nl = r % 20;
        int row = gq * 300 + nt * 20 + nl;
        int ch = __ldcg(&g_char[bt * 16 + bl]);
        sum += g_ge[ch * G4 + row];
        gs[(bl * 20 + nl) * 4 + gq] = sum;
    }
    __syncthreads();

    if (tid < 320) {
        int bl = tid / 20, nl = tid % 20;
        float4 gv = *(const float4*)(gs + (bl * 20 + nl) * 4);
        int bg = bt * 16 + bl, ng = nt * 20 + nl;
        float c_old = g_c[bg * 300 + ng];
        float ig = sigf(gv.x);
        float fg = sigf(gv.y);
        float gg = tanf_(gv.z);
        float og = sigf(gv.w);
        float cn = fg * c_old + ig * gg;
        float hn = og * tanf_(cn);
        g_c[bg * 300 + ng] = cn;
        __stcg(&h_out[bg * 300 + ng], hn);
    }
    __syncthreads();
}

// ---------------- persistent kernel ----------------
__global__ void __launch_bounds__(NTHR, 1)
decoder_persistent(const float* __restrict__ W_phi,
                   const float* __restrict__ b_phi,
                   const float* __restrict__ W_ih,
                   const float* __restrict__ W_hh,
                   const float* __restrict__ W_proj,
                   const float* __restrict__ b_proj,
                   float* __restrict__ out, int write_preds) {
    // 7168 floats: lstm xx tile needs 16*432 = 6912
    __shared__ __align__(16) float sm[7168];
    int cta = blockIdx.x;
    unsigned epoch = 0;

    attend_phase(cta, g_hA, -1, W_phi, b_phi, W_proj, b_proj, out, 0, sm);
    gbar(++epoch);

    for (int s = 0; s < STEPS; ++s) {
        lstm_phase(s & 1, W_ih, W_hh, sm);
        gbar(++epoch);
        attend_phase(cta, (s & 1) ? g_hA : g_hB, s, W_phi, b_phi,
                     W_proj, b_proj, out, write_preds, sm);
        gbar(++epoch);
    }
}

// ---------------- host launcher ----------------
extern "C" void kernel_launch(void* const* d_in, const int* in_sizes, int n_in,
                              void* d_out, int out_size) {
    const float* keys   = (const float*)d_in[0];
    const float* values = (const float*)d_in[1];
    const float* emb    = (const float*)d_in[2];
    const float* W_phi  = (const float*)d_in[3];
    const float* b_phi  = (const float*)d_in[4];
    const float* W_ih   = (const float*)d_in[5];
    const float* b_ih   = (const float*)d_in[6];
    const float* W_hh   = (const float*)d_in[7];
    const float* b_hh   = (const float*)d_in[8];
    const float* W_proj = (const float*)d_in[9];
    const float* b_proj = (const float*)d_in[10];
    const float* h0     = (const float*)d_in[11];
    const float* c0     = (const float*)d_in[12];
    float* out = (float*)d_out;

    int write_preds = (out_size >= STEPS * BB * NV + STEPS * BB) ? 1 : 0;

    init_kernel<<<NV + 1 + TRB, 256>>>(keys, values, emb, W_ih, b_ih, b_hh, h0, c0);
    decoder_persistent<<<NBLK, NTHR>>>(W_phi, b_phi, W_ih, W_hh,
                                       W_proj, b_proj, out, write_preds);
}

// round 8
// speedup vs baseline: 1.0289x; 1.0289x over previous
#include <cuda_runtime.h>
#include <cuda_fp16.h>
#include <math.h>

#define BB    128
#define TT    2048
#define KD    128
#define VD    128
#define HD    300
#define ED    400
#define NV    33
#define G4    1200
#define SOS   5
#define STEPS 500
#define NBLK  128
#define NTHR  1024
#define TRB   256    // value-transpose blocks
#define KTB   4096   // key-transpose tile blocks (128 b x 32 t-tiles)

// ---------------- persistent device state ----------------
__device__ float g_hA[BB * HD];
__device__ float g_hB[BB * HD];
__device__ float g_c[BB * HD];
__device__ float g_ctx[BB * VD];
__device__ float g_ge[NV * G4];   // emb @ W_ih[:, :400]^T + b_ih + b_hh
__device__ int   g_char[BB];
__device__ unsigned g_count;
__device__ volatile unsigned g_sense;
// fp16 copies, uint4-typed for guaranteed 16B alignment:
// keys  [b][k][t]  (t-minor: shuffle-free energy pass)
// values[b][t][v]  (v-minor: shuffle-free value pass)
__device__ uint4 g_keys4[(size_t)BB * KD * (TT / 8)];
__device__ uint4 g_vals4[(size_t)BB * TT * (VD / 8)];

union U4 { uint4 u; __half2 h[4]; };

__device__ __forceinline__ float sigf(float x) { return 1.f / (1.f + __expf(-x)); }
__device__ __forceinline__ float tanf_(float x) { return 2.f / (1.f + __expf(-2.f * x)) - 1.f; }

// ---------------- grid barrier (monotonic epoch) ----------------
__device__ __forceinline__ void gbar(unsigned e) {
    __syncthreads();
    if (threadIdx.x == 0) {
        __threadfence();
        unsigned prev = atomicAdd(&g_count, 1u);
        if (prev == e * NBLK - 1u) {
            g_sense = e;
        } else {
            while (g_sense < e) { }
        }
        __threadfence();
    }
    __syncthreads();
}

// ---------------- init: precompute + transposes + state reset ----------------
__global__ void init_kernel(const float* __restrict__ keys,
                            const float* __restrict__ values,
                            const float* __restrict__ emb,
                            const float* __restrict__ W_ih,
                            const float* __restrict__ b_ih,
                            const float* __restrict__ b_hh,
                            const float* __restrict__ h0,
                            const float* __restrict__ c0) {
    int blk = blockIdx.x, tid = threadIdx.x;
    __shared__ float e_s[ED];
    __shared__ __half hk[KD * 64];   // 16KB key transpose tile [k][t]

    if (blk < NV) {
        for (int i = tid; i < ED; i += blockDim.x) e_s[i] = emb[blk * ED + i];
        __syncthreads();
        int wid = tid >> 5, lane = tid & 31;
        for (int j = wid; j < G4; j += 8) {
            float acc = 0.f;
            const float* wr = W_ih + (size_t)j * 528;
            for (int k = lane; k < ED; k += 32) acc += e_s[k] * wr[k];
            #pragma unroll
            for (int o = 16; o; o >>= 1) acc += __shfl_xor_sync(0xffffffffu, acc, o);
            if (lane == 0) g_ge[blk * G4 + j] = acc + b_ih[j] + b_hh[j];
        }
    } else if (blk == NV) {
        for (int i = tid; i < BB * HD; i += blockDim.x) {
            g_hA[i] = h0[i % HD];
            g_c[i]  = c0[i % HD];
        }
        for (int i = tid; i < BB; i += blockDim.x) g_char[i] = SOS;
        if (tid == 0) { g_count = 0u; g_sense = 0u; }
    } else if (blk < NV + 1 + TRB) {
        // values: [t][b][v] f32 -> [b][t][v] f16
        const int CH = TT * BB * VD / 8;
        int xb = blk - NV - 1;
        for (int c = xb * blockDim.x + tid; c < CH; c += TRB * blockDim.x) {
            const float4* src = (const float4*)values + (size_t)c * 2;
            float4 a = src[0], b4 = src[1];
            U4 o;
            o.h[0] = __floats2half2_rn(a.x, a.y);
            o.h[1] = __floats2half2_rn(a.z, a.w);
            o.h[2] = __floats2half2_rn(b4.x, b4.y);
            o.h[3] = __floats2half2_rn(b4.z, b4.w);
            int kc = c & 15;
            int b  = (c >> 4) & 127;
            int t  = c >> 11;
            g_vals4[((size_t)b * TT + t) * 16 + kc] = o.u;
        }
    } else {
        // keys: [t][b][k] f32 -> [b][k][t] f16 via smem tile (64 t x 128 k)
        int bk = blk - (NV + 1 + TRB);       // 0..4095
        int b  = bk >> 5;
        int tt = (bk & 31) * 64;
        // load tile: thread (t, k4) coalesced along k
        for (int idx = tid; idx < 64 * 32; idx += 256) {
            int t = idx >> 5, k4 = idx & 31;
            float4 v = __ldg((const float4*)(keys + ((size_t)(tt + t) * BB + b) * KD) + k4);
            int k = k4 * 4;
            hk[(k + 0) * 64 + t] = __float2half_rn(v.x);
            hk[(k + 1) * 64 + t] = __float2half_rn(v.y);
            hk[(k + 2) * 64 + t] = __float2half_rn(v.z);
            hk[(k + 3) * 64 + t] = __float2half_rn(v.w);
        }
        __syncthreads();
        // write out: per k-row, 64 t = 8 uint4, coalesced
        for (int idx = tid; idx < 1024; idx += 256) {
            int k = idx >> 3, l8 = idx & 7;
            uint4 o = ((const uint4*)hk)[k * 8 + l8];
            g_keys4[((size_t)b * KD + k) * 256 + (tt >> 3) + l8] = o;
        }
    }
}

// ---------------- attend phase: shuffle-free two-pass softmax attention ----
// smem layout (floats):
//   [0,8192)      epart[4][2048]  (k-slice energy partials); reused as cpart[32][128]
//   [8192,10240)  w_s[2048]
//   [10240,10544) h_s
//   [10544,10672) q_s
//   [10672,10800) ctx_s
//   [10800,10836) lg_s
//   [10836,10868) red
//   [10868,10870) bc
__device__ void attend_phase(int b, const float* __restrict__ hbuf, int s,
                             const float* __restrict__ W_phi,
                             const float* __restrict__ b_phi,
                             const float* __restrict__ W_proj,
                             const float* __restrict__ b_proj,
                             float* __restrict__ out, int write_preds,
                             float* sm) {
    int tid = threadIdx.x, wid = tid >> 5, lane = tid & 31;
    float* epart = sm;
    float* cpart = sm;
    float* w_s   = sm + 8192;
    float* h_s   = sm + 10240;
    float* q_s   = sm + 10544;
    float* ctx_s = sm + 10672;
    float* lg_s  = sm + 10800;
    float* red   = sm + 10836;
    float* bc    = sm + 10868;

    for (int i = tid; i < HD; i += NTHR) h_s[i] = __ldcg(&hbuf[b * HD + i]);
    for (int i = tid; i < VD; i += NTHR) ctx_s[i] = __ldcg(&g_ctx[b * VD + i]);
    __syncthreads();

    if (s >= 0) {
        // logits: h_new + previous context
        for (int v = wid; v < NV; v += 32) {
            float acc = 0.f;
            const float* wr = W_proj + (size_t)v * 428;
            for (int k = lane; k < 428; k += 32) {
                float x = (k < HD) ? h_s[k] : ctx_s[k - HD];
                acc += x * wr[k];
            }
            #pragma unroll
            for (int o = 16; o; o >>= 1) acc += __shfl_xor_sync(0xffffffffu, acc, o);
            if (lane == 0) lg_s[v] = acc + b_proj[v];
        }
        __syncthreads();
        if (tid < NV) out[(size_t)s * (BB * NV) + b * NV + tid] = lg_s[tid];
        if (tid == 0) {
            int am = 0; float mv = lg_s[0];
            for (int v = 1; v < NV; ++v) if (lg_s[v] > mv) { mv = lg_s[v]; am = v; }
            __stcg(&g_char[b], am);
            if (write_preds)
                out[(size_t)STEPS * BB * NV + (size_t)s * BB + b] = (float)am;
        }
    }

    // query = h @ W_phi^T + b_phi
    for (int q = wid; q < KD; q += 32) {
        float acc = 0.f;
        const float* wr = W_phi + (size_t)q * HD;
        for (int k = lane; k < HD; k += 32) acc += h_s[k] * wr[k];
        #pragma unroll
        for (int o = 16; o; o >>= 1) acc += __shfl_xor_sync(0xffffffffu, acc, o);
        if (lane == 0) q_s[q] = acc + b_phi[q];
    }
    __syncthreads();

    // ---- energy pass: keys [b][k][t], lane owns 8 t, NO shuffles ----
    {
        int ttile = (wid >> 2) * 256;        // 8 t-tiles of 256
        int ks    = wid & 3;                 // 4 k-slices of 32
        const uint4* kb = g_keys4 + ((size_t)b * KD + ks * 32) * 256
                        + (ttile >> 3) + lane;
        float e0=0,e1=0,e2=0,e3=0,e4=0,e5=0,e6=0,e7=0;
        #pragma unroll 8
        for (int k = 0; k < 32; k++) {
            U4 kv; kv.u = __ldg(kb + (size_t)k * 256);
            float q = q_s[ks * 32 + k];
            float2 f0 = __half22float2(kv.h[0]);
            float2 f1 = __half22float2(kv.h[1]);
            float2 f2 = __half22float2(kv.h[2]);
            float2 f3 = __half22float2(kv.h[3]);
            e0 += q * f0.x; e1 += q * f0.y; e2 += q * f1.x; e3 += q * f1.y;
            e4 += q * f2.x; e5 += q * f2.y; e6 += q * f3.x; e7 += q * f3.y;
        }
        float4* ep = (float4*)(epart + ks * 2048 + ttile + lane * 8);
        ep[0] = make_float4(e0, e1, e2, e3);
        ep[1] = make_float4(e4, e5, e6, e7);
    }
    __syncthreads();

    // ---- softmax: sum k-slices, global max, exp, sum ----
    float ea, eb;
    {
        int i0 = tid, i1 = tid + 1024;
        ea = epart[i0] + epart[2048 + i0] + epart[4096 + i0] + epart[6144 + i0];
        eb = epart[i1] + epart[2048 + i1] + epart[4096 + i1] + epart[6144 + i1];
        float m = fmaxf(ea, eb);
        #pragma unroll
        for (int o = 16; o; o >>= 1) m = fmaxf(m, __shfl_xor_sync(0xffffffffu, m, o));
        if (lane == 0) red[wid] = m;
    }
    __syncthreads();
    if (wid == 0) {
        float v = red[lane];
        #pragma unroll
        for (int o = 16; o; o >>= 1) v = fmaxf(v, __shfl_xor_sync(0xffffffffu, v, o));
        if (lane == 0) bc[0] = v;
    }
    __syncthreads();
    {
        float M = bc[0];
        float wa = __expf(ea - M), wb = __expf(eb - M);
        w_s[tid] = wa; w_s[tid + 1024] = wb;
        float ls = wa + wb;
        #pragma unroll
        for (int o = 16; o; o >>= 1) ls += __shfl_xor_sync(0xffffffffu, ls, o);
        if (lane == 0) red[wid] = ls;
    }
    __syncthreads();
    if (wid == 0) {
        float v = red[lane];
        #pragma unroll
        for (int o = 16; o; o >>= 1) v += __shfl_xor_sync(0xffffffffu, v, o);
        if (lane == 0) bc[1] = v;
    }
    __syncthreads();   // w_s + bc[1] visible; epart free for cpart reuse

    // ---- value pass: values [b][t][v], lane owns v-chunk, NO shuffles ----
    {
        int kc = lane & 15, ts = lane >> 4;
        const uint4* vb = g_vals4 + (size_t)b * TT * 16;
        float va[8];
        #pragma unroll
        for (int j = 0; j < 8; j++) va[j] = 0.f;

        for (int t0 = wid * 8; t0 < TT; t0 += 256) {    // 8 iters x 8 t
            U4 vv[4]; float w[4];
            #pragma unroll
            for (int i = 0; i < 4; i++) {
                int t = t0 + 2 * i + ts;
                vv[i].u = __ldg(&vb[(size_t)t * 16 + kc]);
                w[i] = w_s[t];
            }
            #pragma unroll
            for (int i = 0; i < 4; i++) {
                float2 f0 = __half22float2(vv[i].h[0]);
                float2 f1 = __half22float2(vv[i].h[1]);
                float2 f2 = __half22float2(vv[i].h[2]);
                float2 f3 = __half22float2(vv[i].h[3]);
                va[0] += w[i] * f0.x; va[1] += w[i] * f0.y;
                va[2] += w[i] * f1.x; va[3] += w[i] * f1.y;
                va[4] += w[i] * f2.x; va[5] += w[i] * f2.y;
                va[6] += w[i] * f3.x; va[7] += w[i] * f3.y;
            }
        }
        // merge t-parity halves
        #pragma unroll
        for (int j = 0; j < 8; j++)
            va[j] += __shfl_xor_sync(0xffffffffu, va[j], 16);
        if (ts == 0) {
            float4* cp = (float4*)(cpart + wid * 128 + kc * 8);
            cp[0] = make_float4(va[0], va[1], va[2], va[3]);
            cp[1] = make_float4(va[4], va[5], va[6], va[7]);
        }
    }
    __syncthreads();

    if (tid < 128) {
        float inv = 1.f / bc[1];
        float acc = 0.f;
        #pragma unroll
        for (int w = 0; w < 32; w++) acc += cpart[w * 128 + tid];
        __stcg(&g_ctx[b * VD + tid], acc * inv);
    }
    __syncthreads();
}

// ---------------- LSTM phase ----------------
__device__ void lstm_phase(int parity,
                           const float* __restrict__ W_ih,
                           const float* __restrict__ W_hh,
                           float* sm) {
    int cta = blockIdx.x;
    if (cta >= 120) return;           // whole CTA exits; per-CTA syncs unaffected
    int tid = threadIdx.x;
    int bt = cta / 15;
    int nt = cta % 15;
    const float* h_in  = parity ? g_hB : g_hA;
    float*       h_out = parity ? g_hA : g_hB;

    float* xx = sm;             // [16][432] = 6912 floats
    for (int idx = tid; idx < 16 * 428; idx += NTHR) {
        int bl = idx / 428, k = idx - bl * 428;
        int bg = bt * 16 + bl;
        float v = (k < 128) ? __ldcg(&g_ctx[bg * 128 + k])
                            : __ldcg(&h_in[bg * 300 + (k - 128)]);
        xx[bl * 432 + k] = v;
    }
    __syncthreads();

    float acc[4][4];
    int ks = 0, rem = 0;
    if (tid < 320) {
        ks = tid / 80; rem = tid % 80;
        int rg = rem / 4, bg = rem % 4;
        int gq = (rg * 4) / 20, rl = (rg * 4) % 20;
        int row0 = gq * 300 + nt * 20 + rl;
        #pragma unroll
        for (int r = 0; r < 4; r++)
            #pragma unroll
            for (int bi = 0; bi < 4; bi++) acc[r][bi] = 0.f;

        int k4s = ks * 27, k4e = (ks == 3) ? 107 : (k4s + 27);
        const float4* xb[4];
        #pragma unroll
        for (int bi = 0; bi < 4; bi++)
            xb[bi] = (const float4*)(xx + (size_t)(bg * 4 + bi) * 432);

        int e1 = k4e < 32 ? k4e : 32;
        for (int k4 = k4s; k4 < e1; k4++) {
            float4 w[4];
            #pragma unroll
            for (int r = 0; r < 4; r++)
                w[r] = __ldg((const float4*)(W_ih + (size_t)(row0 + r) * 528 + 400) + k4);
            #pragma unroll
            for (int bi = 0; bi < 4; bi++) {
                float4 x = xb[bi][k4];
                #pragma unroll
                for (int r = 0; r < 4; r++)
                    acc[r][bi] += w[r].x * x.x + w[r].y * x.y + w[r].z * x.z + w[r].w * x.w;
            }
        }
        int s2 = k4s > 32 ? k4s : 32;
        for (int k4 = s2; k4 < k4e; k4++) {
            float4 w[4];
            #pragma unroll
            for (int r = 0; r < 4; r++)
                w[r] = __ldg((const float4*)(W_hh + (size_t)(row0 + r) * 300) + (k4 - 32));
            #pragma unroll
            for (int bi = 0; bi < 4; bi++) {
                float4 x = xb[bi][k4];
                #pragma unroll
                for (int r = 0; r < 4; r++)
                    acc[r][bi] += w[r].x * x.x + w[r].y * x.y + w[r].z * x.z + w[r].w * x.w;
            }
        }
    }
    __syncthreads();

    float* part = sm;           // 5120 floats
    float* gs   = sm + 5120;    // 1280 floats
    if (tid < 320) {
        #pragma unroll
        for (int r = 0; r < 4; r++)
            #pragma unroll
            for (int bi = 0; bi < 4; bi++)
                part[(rem * 16 + r * 4 + bi) * 4 + ks] = acc[r][bi];
    }
    __syncthreads();

    for (int o = tid; o < 1280; o += NTHR) {
        float sum = part[o * 4] + part[o * 4 + 1] + part[o * 4 + 2] + part[o * 4 + 3];
        int rm = o >> 4, ri = (o >> 2) & 3, bi = o & 3;
        int rg = rm >> 2, bg = rm & 3;
        int r = rg * 4 + ri;
        int bl = bg * 4 + bi;
        int gq = r / 20, nl = r % 20;
        int row = gq * 300 + nt * 20 + nl;
        int ch = __ldcg(&g_char[bt * 16 + bl]);
        sum += g_ge[ch * G4 + row];
        gs[(bl * 20 + nl) * 4 + gq] = sum;
    }
    __syncthreads();

    if (tid < 320) {
        int bl = tid / 20, nl = tid % 20;
        float4 gv = *(const float4*)(gs + (bl * 20 + nl) * 4);
        int bg = bt * 16 + bl, ng = nt * 20 + nl;
        float c_old = g_c[bg * 300 + ng];
        float ig = sigf(gv.x);
        float fg = sigf(gv.y);
        float gg = tanf_(gv.z);
        float og = sigf(gv.w);
        float cn = fg * c_old + ig * gg;
        float hn = og * tanf_(cn);
        g_c[bg * 300 + ng] = cn;
        __stcg(&h_out[bg * 300 + ng], hn);
    }
    __syncthreads();
}

// ---------------- persistent kernel ----------------
__global__ void __launch_bounds__(NTHR, 1)
decoder_persistent(const float* __restrict__ W_phi,
                   const float* __restrict__ b_phi,
                   const float* __restrict__ W_ih,
                   const float* __restrict__ W_hh,
                   const float* __restrict__ W_proj,
                   const float* __restrict__ b_proj,
                   float* __restrict__ out, int write_preds) {
    __shared__ __align__(16) float sm[10880];   // 43.5 KB
    int cta = blockIdx.x;
    unsigned epoch = 0;

    attend_phase(cta, g_hA, -1, W_phi, b_phi, W_proj, b_proj, out, 0, sm);
    gbar(++epoch);

    for (int s = 0; s < STEPS; ++s) {
        lstm_phase(s & 1, W_ih, W_hh, sm);
        gbar(++epoch);
        attend_phase(cta, (s & 1) ? g_hA : g_hB, s, W_phi, b_phi,
                     W_proj, b_proj, out, write_preds, sm);
        gbar(++epoch);
    }
}

// ---------------- host launcher ----------------
extern "C" void kernel_launch(void* const* d_in, const int* in_sizes, int n_in,
                              void* d_out, int out_size) {
    const float* keys   = (const float*)d_in[0];
    const float* values = (const float*)d_in[1];
    const float* emb    = (const float*)d_in[2];
    const float* W_phi  = (const float*)d_in[3];
    const float* b_phi  = (const float*)d_in[4];
    const float* W_ih   = (const float*)d_in[5];
    const float* b_ih   = (const float*)d_in[6];
    const float* W_hh   = (const float*)d_in[7];
    const float* b_hh   = (const float*)d_in[8];
    const float* W_proj = (const float*)d_in[9];
    const float* b_proj = (const float*)d_in[10];
    const float* h0     = (const float*)d_in[11];
    const float* c0     = (const float*)d_in[12];
    float* out = (float*)d_out;

    int write_preds = (out_size >= STEPS * BB * NV + STEPS * BB) ? 1 : 0;

    init_kernel<<<NV + 1 + TRB + KTB, 256>>>(keys, values, emb, W_ih, b_ih,
                                             b_hh, h0, c0);
    decoder_persistent<<<NBLK, NTHR>>>(W_phi, b_phi, W_ih, W_hh,
                                       W_proj, b_proj, out, write_preds);
}